// round 1
// baseline (speedup 1.0000x reference)
#include <cuda_runtime.h>
#include <math_constants.h>

#define IMG_H 64
#define IMG_W 2048
#define NCH   20
#define KNN_CUTOFF 1.0f

// inv_g[k] = 1 - gauss(k)/sum(gauss), sigma=1, 5x5, row-major (ky,kx)
__constant__ float INV_G[25] = {
    0.99703098f, 0.98669378f, 0.97806177f, 0.98669378f, 0.99703098f,
    0.98669378f, 0.94036569f, 0.90167956f, 0.94036569f, 0.98669378f,
    0.97806177f, 0.90167956f, 0.83789717f, 0.90167956f, 0.97806177f,
    0.98669378f, 0.94036569f, 0.90167956f, 0.94036569f, 0.98669378f,
    0.99703098f, 0.98669378f, 0.97806177f, 0.98669378f, 0.99703098f
};

__global__ __launch_bounds__(256)
void knn_kernel(const float* __restrict__ proj_range,
                const float* __restrict__ unproj,
                const float4* __restrict__ probs4,   // [H*W][5] float4 (=20 ch)
                const int*   __restrict__ px,
                const int*   __restrict__ py,
                float4*      __restrict__ out4,      // [P][5] float4
                int P)
{
    int p = blockIdx.x * blockDim.x + threadIdx.x;
    if (p >= P) return;

    const int x0 = px[p];
    const int y0 = py[p];
    const float ur = unproj[p];

    // ---- gather 5x5 range window, compute weighted distances (all in regs) ----
    float d[25];
#pragma unroll
    for (int k = 0; k < 25; ++k) {
        const int yy = y0 + (k / 5) - 2;
        const int xx = x0 + (k % 5) - 2;
        const bool valid = ((unsigned)yy < (unsigned)IMG_H) &&
                           ((unsigned)xx < (unsigned)IMG_W);
        float r = valid ? __ldg(proj_range + yy * IMG_W + xx) : 0.0f;
        if (r < 0.0f) r = CUDART_INF_F;   // matches reference (dead for this data)
        if (k == 12) r = ur;              // center forced to unprojected range
        d[k] = fabsf(r - ur) * INV_G[k];
    }

    float4 a0 = make_float4(0.f, 0.f, 0.f, 0.f);
    float4 a1 = a0, a2 = a0, a3 = a0, a4 = a0;

    // ---- 5 rounds of argmin (stable: strict < keeps lowest index on ties) ----
#pragma unroll
    for (int sel = 0; sel < 5; ++sel) {
        float best = d[0];
        int   bi   = 0;
#pragma unroll
        for (int k = 1; k < 25; ++k) {
            if (d[k] < best) { best = d[k]; bi = k; }
        }
        // knock out the winner without dynamic register indexing
#pragma unroll
        for (int k = 0; k < 25; ++k) {
            if (k == bi) d[k] = CUDART_INF_F;
        }

        const int yy = y0 + bi / 5 - 2;
        const int xx = x0 + bi % 5 - 2;
        const bool ok = (best <= KNN_CUTOFF) &&
                        ((unsigned)yy < (unsigned)IMG_H) &&
                        ((unsigned)xx < (unsigned)IMG_W);
        if (ok) {
            const float4* row = probs4 + (size_t)(yy * IMG_W + xx) * 5;
            float4 v;
            v = __ldg(row + 0); a0.x += v.x; a0.y += v.y; a0.z += v.z; a0.w += v.w;
            v = __ldg(row + 1); a1.x += v.x; a1.y += v.y; a1.z += v.z; a1.w += v.w;
            v = __ldg(row + 2); a2.x += v.x; a2.y += v.y; a2.z += v.z; a2.w += v.w;
            v = __ldg(row + 3); a3.x += v.x; a3.y += v.y; a3.z += v.z; a3.w += v.w;
            v = __ldg(row + 4); a4.x += v.x; a4.y += v.y; a4.z += v.z; a4.w += v.w;
        }
    }

    float4* o = out4 + (size_t)p * 5;
    o[0] = a0; o[1] = a1; o[2] = a2; o[3] = a3; o[4] = a4;
}

extern "C" void kernel_launch(void* const* d_in, const int* in_sizes, int n_in,
                              void* d_out, int out_size)
{
    const float*  proj_range = (const float*)  d_in[0];
    const float*  unproj     = (const float*)  d_in[1];
    const float4* probs4     = (const float4*) d_in[2];
    const int*    px         = (const int*)    d_in[3];
    const int*    py         = (const int*)    d_in[4];
    float4*       out4       = (float4*)       d_out;

    const int P = in_sizes[1];          // unproj_range element count
    const int threads = 256;
    const int blocks = (P + threads - 1) / threads;
    knn_kernel<<<blocks, threads>>>(proj_range, unproj, probs4, px, py, out4, P);
}

// round 2
// speedup vs baseline: 1.0208x; 1.0208x over previous
#include <cuda_runtime.h>
#include <math_constants.h>

#define IMG_H 64
#define IMG_W 2048
#define NCH   20
#define KNN_CUTOFF 1.0f

// inv_g[k] = 1 - gauss(k)/sum(gauss), sigma=1, 5x5, row-major (ky,kx)
__constant__ float INV_G[25] = {
    0.99703098f, 0.98669378f, 0.97806177f, 0.98669378f, 0.99703098f,
    0.98669378f, 0.94036569f, 0.90167956f, 0.94036569f, 0.98669378f,
    0.97806177f, 0.90167956f, 0.83789717f, 0.90167956f, 0.97806177f,
    0.98669378f, 0.94036569f, 0.90167956f, 0.94036569f, 0.98669378f,
    0.99703098f, 0.98669378f, 0.97806177f, 0.98669378f, 0.99703098f
};

__global__ __launch_bounds__(256)
void knn_kernel(const float* __restrict__ proj_range,
                const float* __restrict__ unproj,
                const float4* __restrict__ probs4,   // [H*W][5] float4 (=20 ch)
                const int*   __restrict__ px,
                const int*   __restrict__ py,
                float4*      __restrict__ out4,      // [P][5] float4
                int P)
{
    int p = blockIdx.x * blockDim.x + threadIdx.x;
    if (p >= P) return;

    const int x0 = px[p];
    const int y0 = py[p];
    const float ur = unproj[p];

    // ---- gather 5x5 range window, compute weighted distances (all in regs) ----
    float d[25];
#pragma unroll
    for (int k = 0; k < 25; ++k) {
        const int yy = y0 + (k / 5) - 2;
        const int xx = x0 + (k % 5) - 2;
        const bool valid = ((unsigned)yy < (unsigned)IMG_H) &&
                           ((unsigned)xx < (unsigned)IMG_W);
        float r = valid ? __ldg(proj_range + yy * IMG_W + xx) : 0.0f;
        if (r < 0.0f) r = CUDART_INF_F;   // matches reference (dead for this data)
        if (k == 12) r = ur;              // center forced to unprojected range
        d[k] = fabsf(r - ur) * INV_G[k];
    }

    float4 a0 = make_float4(0.f, 0.f, 0.f, 0.f);
    float4 a1 = a0, a2 = a0, a3 = a0, a4 = a0;

    // ---- 5 rounds of argmin (stable: strict < keeps lowest index on ties) ----
#pragma unroll
    for (int sel = 0; sel < 5; ++sel) {
        float best = d[0];
        int   bi   = 0;
#pragma unroll
        for (int k = 1; k < 25; ++k) {
            if (d[k] < best) { best = d[k]; bi = k; }
        }
        // knock out the winner without dynamic register indexing
#pragma unroll
        for (int k = 0; k < 25; ++k) {
            if (k == bi) d[k] = CUDART_INF_F;
        }

        const int yy = y0 + bi / 5 - 2;
        const int xx = x0 + bi % 5 - 2;
        const bool ok = (best <= KNN_CUTOFF) &&
                        ((unsigned)yy < (unsigned)IMG_H) &&
                        ((unsigned)xx < (unsigned)IMG_W);
        if (ok) {
            const float4* row = probs4 + (size_t)(yy * IMG_W + xx) * 5;
            float4 v;
            v = __ldg(row + 0); a0.x += v.x; a0.y += v.y; a0.z += v.z; a0.w += v.w;
            v = __ldg(row + 1); a1.x += v.x; a1.y += v.y; a1.z += v.z; a1.w += v.w;
            v = __ldg(row + 2); a2.x += v.x; a2.y += v.y; a2.z += v.z; a2.w += v.w;
            v = __ldg(row + 3); a3.x += v.x; a3.y += v.y; a3.z += v.z; a3.w += v.w;
            v = __ldg(row + 4); a4.x += v.x; a4.y += v.y; a4.z += v.z; a4.w += v.w;
        }
    }

    float4* o = out4 + (size_t)p * 5;
    o[0] = a0; o[1] = a1; o[2] = a2; o[3] = a3; o[4] = a4;
}

extern "C" void kernel_launch(void* const* d_in, const int* in_sizes, int n_in,
                              void* d_out, int out_size)
{
    const float*  proj_range = (const float*)  d_in[0];
    const float*  unproj     = (const float*)  d_in[1];
    const float4* probs4     = (const float4*) d_in[2];
    const int*    px         = (const int*)    d_in[3];
    const int*    py         = (const int*)    d_in[4];
    float4*       out4       = (float4*)       d_out;

    const int P = in_sizes[1];          // unproj_range element count
    const int threads = 256;
    const int blocks = (P + threads - 1) / threads;
    knn_kernel<<<blocks, threads>>>(proj_range, unproj, probs4, px, py, out4, P);
}

// round 3
// speedup vs baseline: 1.2089x; 1.1843x over previous
#include <cuda_runtime.h>
#include <math_constants.h>

#define IMG_H 64
#define IMG_W 2048
#define KNN_CUTOFF 1.0f
#define P_CAP 131072

// inv_g[k] = 1 - gauss(k)/sum(gauss), sigma=1, 5x5, row-major (ky,kx)
__constant__ float INV_G[25] = {
    0.99703098f, 0.98669378f, 0.97806177f, 0.98669378f, 0.99703098f,
    0.98669378f, 0.94036569f, 0.90167956f, 0.94036569f, 0.98669378f,
    0.97806177f, 0.90167956f, 0.83789717f, 0.90167956f, 0.97806177f,
    0.98669378f, 0.94036569f, 0.90167956f, 0.94036569f, 0.98669378f,
    0.99703098f, 0.98669378f, 0.97806177f, 0.98669378f, 0.99703098f
};

// per point: 5 winner linear offsets into the HxW image, or -1 if masked
__device__ int g_winners[P_CAP * 5];

// ---------------------------------------------------------------------------
// Kernel A: selection only. 1 thread/point. Integer-key argmin (all lat-4 ops).
// ---------------------------------------------------------------------------
__global__ __launch_bounds__(128)
void knn_select(const float* __restrict__ proj_range,
                const float* __restrict__ unproj,
                const int*   __restrict__ px,
                const int*   __restrict__ py,
                int P)
{
    int p = blockIdx.x * blockDim.x + threadIdx.x;
    if (p >= P) return;

    const int x0 = px[p];
    const int y0 = py[p];
    const float ur = unproj[p];

    // gather 5x5 range window; keys = float bits (d >= 0 so u32 order == float order)
    unsigned key[25];
#pragma unroll
    for (int k = 0; k < 25; ++k) {
        const int yy = y0 + (k / 5) - 2;
        const int xx = x0 + (k % 5) - 2;
        const bool valid = ((unsigned)yy < (unsigned)IMG_H) &&
                           ((unsigned)xx < (unsigned)IMG_W);
        float r = valid ? __ldg(proj_range + yy * IMG_W + xx) : 0.0f;
        if (r < 0.0f) r = CUDART_INF_F;     // matches reference (dead for this data)
        if (k == 12) r = ur;                // center forced to unprojected range
        key[k] = __float_as_uint(fabsf(r - ur) * INV_G[k]);
    }

    int* wout = g_winners + (size_t)p * 5;

#pragma unroll
    for (int sel = 0; sel < 5; ++sel) {
        // --- value min-tree (depth 5, IMNMX lat 4) ---
        unsigned v[32];
#pragma unroll
        for (int k = 0; k < 25; ++k) v[k] = key[k];
#pragma unroll
        for (int k = 25; k < 32; ++k) v[k] = 0xFFFFFFFFu;
#pragma unroll
        for (int s = 16; s >= 1; s >>= 1) {
#pragma unroll
            for (int i = 0; i < s; ++i) v[i] = min(v[i], v[i + s]);
        }
        const unsigned m = v[0];

        // --- index-of-min tree (lowest index on ties) ---
        unsigned ix[32];
#pragma unroll
        for (int k = 0; k < 25; ++k) ix[k] = (key[k] == m) ? (unsigned)k : 32u;
#pragma unroll
        for (int k = 25; k < 32; ++k) ix[k] = 32u;
#pragma unroll
        for (int s = 16; s >= 1; s >>= 1) {
#pragma unroll
            for (int i = 0; i < s; ++i) ix[i] = min(ix[i], ix[i + s]);
        }
        const unsigned bi = ix[0];

        // knock out the winner (parallel predicated, no dynamic indexing)
#pragma unroll
        for (int k = 0; k < 25; ++k) {
            if ((unsigned)k == bi) key[k] = 0xFFFFFFFFu;
        }

        const int byy = y0 + (int)(bi / 5u) - 2;
        const int bxx = x0 + (int)(bi % 5u) - 2;
        const bool ok = (__uint_as_float(m) <= KNN_CUTOFF) &&
                        ((unsigned)byy < (unsigned)IMG_H) &&
                        ((unsigned)bxx < (unsigned)IMG_W);
        wout[sel] = ok ? (byy * IMG_W + bxx) : -1;
    }
}

// ---------------------------------------------------------------------------
// Kernel B: accumulation. 5 threads/point (one float4 chunk each). Pure memory.
// ---------------------------------------------------------------------------
__global__ __launch_bounds__(256)
void knn_gather(const float4* __restrict__ probs4,   // [H*W][5] float4 (=20 ch)
                float4*       __restrict__ out4,     // [P][5] float4
                int P)
{
    int t = blockIdx.x * blockDim.x + threadIdx.x;
    if (t >= P * 5) return;

    const int p = t / 5;
    const int c = t - p * 5;

    const int* w = g_winners + (size_t)p * 5;
    const int o0 = w[0], o1 = w[1], o2 = w[2], o3 = w[3], o4 = w[4];

    float4 acc = make_float4(0.f, 0.f, 0.f, 0.f);
    float4 vv;
    if (o0 >= 0) { vv = __ldg(probs4 + (size_t)o0 * 5 + c); acc.x += vv.x; acc.y += vv.y; acc.z += vv.z; acc.w += vv.w; }
    if (o1 >= 0) { vv = __ldg(probs4 + (size_t)o1 * 5 + c); acc.x += vv.x; acc.y += vv.y; acc.z += vv.z; acc.w += vv.w; }
    if (o2 >= 0) { vv = __ldg(probs4 + (size_t)o2 * 5 + c); acc.x += vv.x; acc.y += vv.y; acc.z += vv.z; acc.w += vv.w; }
    if (o3 >= 0) { vv = __ldg(probs4 + (size_t)o3 * 5 + c); acc.x += vv.x; acc.y += vv.y; acc.z += vv.z; acc.w += vv.w; }
    if (o4 >= 0) { vv = __ldg(probs4 + (size_t)o4 * 5 + c); acc.x += vv.x; acc.y += vv.y; acc.z += vv.z; acc.w += vv.w; }

    out4[t] = acc;   // out index == p*5 + c == t, fully coalesced
}

extern "C" void kernel_launch(void* const* d_in, const int* in_sizes, int n_in,
                              void* d_out, int out_size)
{
    const float*  proj_range = (const float*)  d_in[0];
    const float*  unproj     = (const float*)  d_in[1];
    const float4* probs4     = (const float4*) d_in[2];
    const int*    px         = (const int*)    d_in[3];
    const int*    py         = (const int*)    d_in[4];
    float4*       out4       = (float4*)       d_out;

    int P = in_sizes[1];                 // unproj_range element count
    if (P > P_CAP) P = P_CAP;            // scratch capacity guard (fixed-shape problem)

    {
        const int threads = 128;
        const int blocks = (P + threads - 1) / threads;
        knn_select<<<blocks, threads>>>(proj_range, unproj, px, py, P);
    }
    {
        const int threads = 256;
        const int total = P * 5;
        const int blocks = (total + threads - 1) / threads;
        knn_gather<<<blocks, threads>>>(probs4, out4, P);
    }
}